// round 15
// baseline (speedup 1.0000x reference)
#include <cuda_runtime.h>
#include <cuda_bf16.h>

#define L 45
#define LP 48              // padded label count
#define SMAX 512
#define START_IDX 43
#define STOP_IDX 44
#define PF 4               // logit prefetch distance
#define NB 1024            // batch size (fixed for this problem)
#define LOG2E 1.4426950408889634f
#define LN2   0.6931471805599453f

__device__ __forceinline__ float ex2f(float x) {
    float r; asm("ex2.approx.ftz.f32 %0, %1;" : "=f"(r) : "f"(x)); return r;
}
__device__ __forceinline__ float lg2f(float x) {
    float r; asm("lg2.approx.ftz.f32 %0, %1;" : "=f"(r) : "f"(x)); return r;
}
__device__ __forceinline__ void fma2(unsigned long long& d,
                                     unsigned long long a, unsigned long long b) {
    asm("fma.rn.f32x2 %0, %1, %2, %0;" : "+l"(d) : "l"(a), "l"(b));
}
__device__ __forceinline__ void add2(unsigned long long& d, unsigned long long a) {
    asm("add.rn.f32x2 %0, %0, %1;" : "+l"(d) : "l"(a));
}
__device__ __forceinline__ unsigned long long pack2(float lo, float hi) {
    unsigned long long v;
    asm("mov.b64 %0, {%1, %2};" : "=l"(v) : "f"(lo), "f"(hi)); return v;
}
__device__ __forceinline__ float2 unpack2(unsigned long long v) {
    float2 f; asm("mov.b64 {%0, %1}, %2;" : "=f"(f.x), "=f"(f.y) : "l"(v)); return f;
}

// permutation of batch indices, sorted by descending length
__device__ int d_perm[NB];

// ---- pre-pass: bitonic sort of (len desc, idx) keys, one 1024-thread block ----
__global__ void sort_lens_kernel(const int* __restrict__ lens, int B) {
    __shared__ unsigned sk[NB];
    const int t = threadIdx.x;
    const int len = (t < B) ? lens[t] : 0;
    sk[t] = ((unsigned)(SMAX - len) << 12) | (unsigned)t;
    __syncthreads();
    for (int k = 2; k <= NB; k <<= 1) {
        for (int j = k >> 1; j > 0; j >>= 1) {
            const int ixj = t ^ j;
            if (ixj > t) {
                const unsigned a = sk[t], c = sk[ixj];
                const bool up = ((t & k) == 0);
                if (up ? (a > c) : (a < c)) { sk[t] = c; sk[ixj] = a; }
            }
            __syncthreads();
        }
    }
    d_perm[t] = (int)(sk[t] & 0xFFFu);
}

// ---- main kernel: R3 step body, SOFTWARE-PIPELINED x2 ----
// The R14 experiment proved the step is LATENCY-bound (~550 cyc of mostly
// dead time), so each barrier interval now advances TWO independent batches
// (A, B) one step each: B's dot issues into A's chain bubbles. Same 2 warps,
// same single BAR0 per interval (no extra arrival skew -- the R5/R7/R9/R13
// poison). rowp (expT in regs) is shared by both dots.
// 256 blocks x 64 thr; block j interleaves sorted-adjacent batches
// perm[2j], perm[2j+1] (freeze padding ~0), then the mirror pair
// perm[1022-2j], perm[1023-2j]: every block ~513 barrier-steps, 4 batches.
// Per batch, thread i: i<45 e-producers, i==45 scale-increment producer.
// Recurrence (base-2, scaled-linear): s_i = sum_j expT[i,j]*e[j];
//   e'_i = s_i * 2^(lgt2_i - c2);  M2 += c2;  c2' = lg2(s_0)+lgt2_0-c2 (stale).
__global__ __launch_bounds__(64) void crf_fwd_kernel(
    const float* __restrict__ logits,      // [B, S, L]
    const int*   __restrict__ lens,        // [B]
    const float* __restrict__ trans,       // [L, L], trans[i*L+j]=score(j->i)
    float*       __restrict__ out)         // [B]
{
    const int i = threadIdx.x;

    __shared__ __align__(16) float e_sm[2][2][LP];   // [batch][phase][label]
    __shared__ float c_sm[2][2];                     // [batch][phase]
    __shared__ float m_sm[2];
    __shared__ float red[2][64];

    const bool is_e = (i < L);
    const bool is_c = (i == L);            // thread 45
    const bool ld   = is_e | is_c;
    const int  lab  = is_e ? i : 0;

    // packed expT row in registers (shared by ALL batches -- same trans)
    unsigned long long rowp[LP / 2];
#pragma unroll
    for (int m = 0; m < LP / 2; m++) rowp[m] = 0ull;
    if (ld) {
#pragma unroll
        for (int m = 0; m < LP / 2; m++) {
            const float x0 = __expf(trans[lab * L + 2 * m]);
            const float x1 = (2 * m + 1 < L) ? __expf(trans[lab * L + 2 * m + 1]) : 0.f;
            rowp[m] = pack2(x0, x1);
        }
    }

    for (int q = 0; q < 2; q++) {
        const int iA = (q == 0) ? (2 * blockIdx.x)     : (1022 - 2 * blockIdx.x);
        const int iB = (q == 0) ? (2 * blockIdx.x + 1) : (1023 - 2 * blockIdx.x);
        const int bA = d_perm[iA];
        const int bB = d_perm[iB];

        if (i < LP) {
            e_sm[0][0][i] = 0.f; e_sm[0][1][i] = 0.f;
            e_sm[1][0][i] = 0.f; e_sm[1][1][i] = 0.f;
        }
        if (i == 0) { c_sm[0][0] = 0.f; c_sm[0][1] = 0.f;
                      c_sm[1][0] = 0.f; c_sm[1][1] = 0.f; }

        const int lenA = lens[bA];
        const int lenB = lens[bB];
        const int lmax = max(lenA, lenB);
        const float* lgA = logits + (size_t)bA * SMAX * L;
        const float* lgB = logits + (size_t)bB * SMAX * L;

        // ---- t = 0 analytically for both: alpha0 = logit[0] + T[:, START] ----
        float a0A = 0.f, a0B = 0.f;
        if (is_e) {
            const float tS = trans[i * L + START_IDX];
            a0A = lgA[i] + tS;
            a0B = lgB[i] + tS;
        }
        if (i == 0) { m_sm[0] = a0A; m_sm[1] = a0B; }
        __syncthreads();
        const float mu0A = m_sm[0], mu0B = m_sm[1];
        float M2A = mu0A * LOG2E, M2B = mu0B * LOG2E;
        float eLA = ex2f((a0A - mu0A) * LOG2E);
        float eLB = ex2f((a0B - mu0B) * LOG2E);
        if (is_e) { e_sm[0][1][i] = eLA; e_sm[1][1][i] = eLB; }

        // ---- prefetch logits for both (pre-scaled by log2e) ----
        float bufA[PF], bufB[PF];
#pragma unroll
        for (int u = 0; u < PF; u++) {
            const int t = 1 + u;
            bufA[u] = (ld && t < lenA) ? lgA[t * L + lab] * LOG2E : 0.f;
            bufB[u] = (ld && t < lenB) ? lgB[t * L + lab] * LOG2E : 0.f;
        }

#define STEP2(tt, uu) do {                                                    \
        const int p_ = (tt) & 1;                                              \
        __syncthreads();                                                      \
        const bool aA_ = ((tt) < lenA);                                       \
        const bool aB_ = ((tt) < lenB);                                       \
        const float ltA_ = bufA[uu];                                          \
        const float ltB_ = bufB[uu];                                          \
        { const int tn_ = (tt) + PF;                                          \
          bufA[uu] = (ld && tn_ < lenA) ? lgA[tn_ * L + lab] * LOG2E : 0.f;   \
          bufB[uu] = (ld && tn_ < lenB) ? lgB[tn_ * L + lab] * LOG2E : 0.f; } \
        const float cA_ = c_sm[0][p_ ^ 1];                                    \
        const float cB_ = c_sm[1][p_ ^ 1];                                    \
        const ulonglong2* eA_ = (const ulonglong2*)(e_sm[0][p_]);             \
        const ulonglong2* eB_ = (const ulonglong2*)(e_sm[1][p_]);             \
        unsigned long long kA_[4] = {0,0,0,0}, kB_[4] = {0,0,0,0};            \
        _Pragma("unroll")                                                     \
        for (int h_ = 0; h_ < LP / 4; h_++) {                                 \
            const ulonglong2 wA_ = eA_[h_];                                   \
            const ulonglong2 wB_ = eB_[h_];                                   \
            fma2(kA_[(2 * h_)     & 3], rowp[2 * h_],     wA_.x);             \
            fma2(kB_[(2 * h_)     & 3], rowp[2 * h_],     wB_.x);             \
            fma2(kA_[(2 * h_ + 1) & 3], rowp[2 * h_ + 1], wA_.y);             \
            fma2(kB_[(2 * h_ + 1) & 3], rowp[2 * h_ + 1], wB_.y);             \
        }                                                                     \
        add2(kA_[0], kA_[2]); add2(kA_[1], kA_[3]); add2(kA_[0], kA_[1]);     \
        add2(kB_[0], kB_[2]); add2(kB_[1], kB_[3]); add2(kB_[0], kB_[1]);     \
        const float2 fA_ = unpack2(kA_[0]);                                   \
        const float2 fB_ = unpack2(kB_[0]);                                   \
        const float sA_ = fA_.x + fA_.y;                                      \
        const float sB_ = fB_.x + fB_.y;                                      \
        const float nA_ = sA_ * ex2f(ltA_ - cA_);                             \
        const float nB_ = sB_ * ex2f(ltB_ - cB_);                             \
        if (is_e) {                                                           \
            eLA = aA_ ? nA_ : eLA;  e_sm[0][p_ ^ 1][i] = eLA;                 \
            eLB = aB_ ? nB_ : eLB;  e_sm[1][p_ ^ 1][i] = eLB;                 \
        }                                                                     \
        if (is_c) {                                                           \
            c_sm[0][p_] = aA_ ? (lg2f(sA_) + ltA_ - cA_) : cA_;               \
            c_sm[1][p_] = aB_ ? (lg2f(sB_) + ltB_ - cB_) : cB_;               \
        }                                                                     \
        M2A += aA_ ? cA_ : 0.f;                                               \
        M2B += aB_ ? cB_ : 0.f;                                               \
    } while (0)

        // main loop to lmax (sorted-adjacent lens => ~zero padding)
        int t = 1;
        for (; t + PF <= lmax; t += PF) {
            STEP2(t + 0, 0);
            STEP2(t + 1, 1);
            STEP2(t + 2, 2);
            STEP2(t + 3, 3);
        }
        if (t < lmax) { STEP2(t, 0); t++; }
        if (t < lmax) { STEP2(t, 1); t++; }
        if (t < lmax) { STEP2(t, 2); }
#undef STEP2

        // ---- epilogue: out[b] = LSE_i( alpha_i + T[STOP, i] ) for both ----
        {
            const float tE = is_e ? trans[STOP_IDX * L + lab] : 0.f;
            red[0][i] = is_e ? ((M2A + lg2f(eLA)) * LN2 + tE) : -1e30f;
            red[1][i] = is_e ? ((M2B + lg2f(eLB)) * LN2 + tE) : -1e30f;
        }
        __syncthreads();
        if (i == 0) {
            float m0 = red[0][0], m1 = red[1][0];
#pragma unroll
            for (int j = 1; j < L; j++) {
                m0 = fmaxf(m0, red[0][j]);
                m1 = fmaxf(m1, red[1][j]);
            }
            float s0 = 0.f, s1 = 0.f;
#pragma unroll
            for (int j = 0; j < L; j++) {
                s0 += __expf(red[0][j] - m0);
                s1 += __expf(red[1][j] - m1);
            }
            out[bA] = m0 + __logf(s0);
            out[bB] = m1 + __logf(s1);
        }
        __syncthreads();   // protect smem re-init of next round
    }
}

extern "C" void kernel_launch(void* const* d_in, const int* in_sizes, int n_in,
                              void* d_out, int out_size) {
    const float* logits = (const float*)d_in[0];   // [1024, 512, 45] f32
    const int*   lens   = (const int*)d_in[1];     // [1024] i32
    const float* trans  = (const float*)d_in[2];   // [45, 45] f32
    float* out = (float*)d_out;                    // [1024] f32

    const int B = in_sizes[1];                     // 1024
    sort_lens_kernel<<<1, NB>>>(lens, B);
    crf_fwd_kernel<<<B / 4, 64>>>(logits, lens, trans, out);
}

// round 16
// speedup vs baseline: 1.0307x; 1.0307x over previous
#include <cuda_runtime.h>
#include <cuda_bf16.h>

#define L 45
#define LP 48              // padded label count
#define SMAX 512
#define START_IDX 43
#define STOP_IDX 44
#define PF 4               // logit prefetch distance
#define NB 1024            // batch size (fixed for this problem)
#define LOG2E 1.4426950408889634f
#define LN2   0.6931471805599453f

__device__ __forceinline__ float ex2f(float x) {
    float r; asm("ex2.approx.ftz.f32 %0, %1;" : "=f"(r) : "f"(x)); return r;
}
__device__ __forceinline__ float lg2f(float x) {
    float r; asm("lg2.approx.ftz.f32 %0, %1;" : "=f"(r) : "f"(x)); return r;
}
__device__ __forceinline__ void fma2(unsigned long long& d,
                                     unsigned long long a, unsigned long long b) {
    asm("fma.rn.f32x2 %0, %1, %2, %0;" : "+l"(d) : "l"(a), "l"(b));
}
__device__ __forceinline__ void add2(unsigned long long& d, unsigned long long a) {
    asm("add.rn.f32x2 %0, %0, %1;" : "+l"(d) : "l"(a));
}
__device__ __forceinline__ unsigned long long pack2(float lo, float hi) {
    unsigned long long v;
    asm("mov.b64 %0, {%1, %2};" : "=l"(v) : "f"(lo), "f"(hi)); return v;
}
__device__ __forceinline__ float2 unpack2(unsigned long long v) {
    float2 f; asm("mov.b64 {%0, %1}, %2;" : "=f"(f.x), "=f"(f.y) : "l"(v)); return f;
}

// permutation of batch indices, sorted by descending length
__device__ int d_perm[NB];

// ---- pre-pass: bitonic sort of (len desc, idx) keys, one 1024-thread block ----
__global__ void sort_lens_kernel(const int* __restrict__ lens, int B) {
    __shared__ unsigned sk[NB];
    const int t = threadIdx.x;
    const int len = (t < B) ? lens[t] : 0;
    sk[t] = ((unsigned)(SMAX - len) << 12) | (unsigned)t;
    __syncthreads();
    for (int k = 2; k <= NB; k <<= 1) {
        for (int j = k >> 1; j > 0; j >>= 1) {
            const int ixj = t ^ j;
            if (ixj > t) {
                const unsigned a = sk[t], c = sk[ixj];
                const bool up = ((t & k) == 0);
                if (up ? (a > c) : (a < c)) { sk[t] = c; sk[ixj] = a; }
            }
            __syncthreads();
        }
    }
    d_perm[t] = (int)(sk[t] & 0xFFFu);
}

// ---- main kernel: R14 step body + bin-packing, on SMSP-SPREAD warp pairs ----
// 128-thread blocks; TWO warps exit immediately, the surviving pair is chosen
// by (bid>>1)&1:  half 0 -> warps {0,3} (SMSP 0,3), half 1 -> {1,2} (SMSP
// 1,2). Co-resident blocks differ in bid by 148 (odd/2) so halves ALTERNATE
// across waves on each SM -> all four SMSPs carry ~1.73 warps instead of
// SMSP0/1 carrying 3.46 (the R3/R14 issue-contention wall). Sync stays the
// cheap plain __syncthreads among the two live warps (R8-proven pattern).
// Bin-packing: block j runs batch perm[j] (long) then perm[1023-j] (short)
// sequentially -> every block ~513 steps, no tail, uniform contention.
// Chain tweak: x = 2^(lgt2 - c) is computed right after the barrier, BEFORE
// the dot (independent of e), hiding the ex2 under the LDS+FMA chain.
// Per batch, thread i: i<45 e-producers (expT row in regs, packed f32x2
// j-dot), i==45 dedicated scale-increment producer.
// Recurrence (base-2, scaled-linear): s_i = sum_j expT[i,j]*e[j];
//   e'_i = s_i * x_i;  M2 += c2;  c2' = lg2(s_0) + lgt2_0 - c2 (stale).
__global__ __launch_bounds__(128) void crf_fwd_kernel(
    const float* __restrict__ logits,      // [B, S, L]
    const int*   __restrict__ lens,        // [B]
    const float* __restrict__ trans,       // [L, L], trans[i*L+j]=score(j->i)
    float*       __restrict__ out)         // [B]
{
    const int wid  = threadIdx.x >> 5;
    const int lane = threadIdx.x & 31;
    const int half = (blockIdx.x >> 1) & 1;        // alternates across waves
    // half 0 keeps warps {0,3}; half 1 keeps warps {1,2}; others exit now.
    const bool keep = half ? (wid == 1 || wid == 2) : (wid == 0 || wid == 3);
    if (!keep) return;
    const bool lowhalf = (wid == 0 || wid == 1);   // which 32 labels
    const int  i = (lowhalf ? 0 : 32) + lane;      // label index 0..63

    __shared__ __align__(16) float e_s[2][LP];
    __shared__ float c_s[2];
    __shared__ float m_s;
    __shared__ float red[64];

    const bool is_e = (i < L);
    const bool is_c = (i == L);            // thread 45
    const bool ld   = is_e | is_c;
    const int  lab  = is_e ? i : 0;

    // packed expT row in registers (shared by both batches -- same trans)
    unsigned long long rowp[LP / 2];
#pragma unroll
    for (int m = 0; m < LP / 2; m++) rowp[m] = 0ull;
    if (ld) {
#pragma unroll
        for (int m = 0; m < LP / 2; m++) {
            const float x0 = __expf(trans[lab * L + 2 * m]);
            const float x1 = (2 * m + 1 < L) ? __expf(trans[lab * L + 2 * m + 1]) : 0.f;
            rowp[m] = pack2(x0, x1);
        }
    }

    for (int q = 0; q < 2; q++) {
        const int b = d_perm[q == 0 ? blockIdx.x : (NB - 1 - blockIdx.x)];

        if (i < LP) { e_s[0][i] = 0.f; e_s[1][i] = 0.f; }
        if (i == 0) { c_s[0] = 0.f; c_s[1] = 0.f; }

        const int len = lens[b];
        const float* lg = logits + (size_t)b * SMAX * L;

        // ---- t = 0 analytically: alpha0 = logit[0] + T[:, START] ----
        float a0v = 0.f;
        if (is_e) a0v = lg[i] + trans[i * L + START_IDX];
        if (i == 0) m_s = a0v;
        __syncthreads();
        const float mu0 = m_s;
        float M2 = mu0 * LOG2E;            // running scale (base-2)
        float e_loc = ex2f((a0v - mu0) * LOG2E);
        if (is_e) e_s[1][i] = e_loc;

        // ---- prefetch logits (pre-scaled by log2e) ----
        float lgbuf[PF];
#pragma unroll
        for (int u = 0; u < PF; u++) {
            const int t = 1 + u;
            lgbuf[u] = (ld && t < len) ? lg[t * L + lab] * LOG2E : 0.f;
        }

#define STEP(tt, uu) do {                                                     \
        const int p_ = (tt) & 1;                                              \
        __syncthreads();                                                      \
        const float lgt2_ = lgbuf[uu];                                        \
        const float c2_ = c_s[p_ ^ 1];                                        \
        const float x_ = ex2f(lgt2_ - c2_);  /* off e-chain: starts early */  \
        { const int tn_ = (tt) + PF;                                          \
          lgbuf[uu] = (ld && tn_ < len) ? lg[tn_ * L + lab] * LOG2E : 0.f; }  \
        const ulonglong2* e2_ = (const ulonglong2*)(e_s[p_]);                 \
        unsigned long long ac_[8] = {0,0,0,0,0,0,0,0};                        \
        _Pragma("unroll")                                                     \
        for (int h_ = 0; h_ < LP / 4; h_++) {                                 \
            const ulonglong2 w_ = e2_[h_];                                    \
            fma2(ac_[(2 * h_)     & 7], rowp[2 * h_],     w_.x);              \
            fma2(ac_[(2 * h_ + 1) & 7], rowp[2 * h_ + 1], w_.y);              \
        }                                                                     \
        add2(ac_[0], ac_[4]); add2(ac_[1], ac_[5]);                           \
        add2(ac_[2], ac_[6]); add2(ac_[3], ac_[7]);                           \
        add2(ac_[0], ac_[2]); add2(ac_[1], ac_[3]);                           \
        add2(ac_[0], ac_[1]);                                                 \
        const float2 f_ = unpack2(ac_[0]);                                    \
        const float s_ = f_.x + f_.y;                                         \
        if (is_e) {                                                           \
            const float en_ = s_ * x_;                                        \
            e_s[p_ ^ 1][i] = en_; e_loc = en_;                                \
        }                                                                     \
        if (is_c) c_s[p_] = lg2f(s_) + lgt2_ - c2_;                           \
        M2 += c2_;                                                            \
    } while (0)

        // main loop: full PF-chunks, branch-free bodies
        int t = 1;
        for (; t + PF <= len; t += PF) {
            STEP(t + 0, 0);
            STEP(t + 1, 1);
            STEP(t + 2, 2);
            STEP(t + 3, 3);
        }
        // tail (<= 3 steps), constant lgbuf indices
        if (t < len) { STEP(t, 0); t++; }
        if (t < len) { STEP(t, 1); t++; }
        if (t < len) { STEP(t, 2); }
#undef STEP

        // ---- epilogue: out[b] = LSE_i( alpha_i + T[STOP, i] ) ----
        red[i] = is_e ? ((M2 + lg2f(e_loc)) * LN2 + trans[STOP_IDX * L + i]) : -1e30f;
        __syncthreads();
        if (i == 0) {
            float m = red[0];
#pragma unroll
            for (int j = 1; j < L; j++) m = fmaxf(m, red[j]);
            float s = 0.f;
#pragma unroll
            for (int j = 0; j < L; j++) s += __expf(red[j] - m);
            out[b] = m + __logf(s);
        }
        __syncthreads();   // protect smem re-init of next batch
    }
}

extern "C" void kernel_launch(void* const* d_in, const int* in_sizes, int n_in,
                              void* d_out, int out_size) {
    const float* logits = (const float*)d_in[0];   // [1024, 512, 45] f32
    const int*   lens   = (const int*)d_in[1];     // [1024] i32
    const float* trans  = (const float*)d_in[2];   // [45, 45] f32
    float* out = (float*)d_out;                    // [1024] f32

    const int B = in_sizes[1];                     // 1024
    sort_lens_kernel<<<1, NB>>>(lens, B);
    crf_fwd_kernel<<<B / 2, 128>>>(logits, lens, trans, out);
}